// round 10
// baseline (speedup 1.0000x reference)
#include <cuda_runtime.h>
#include <cuda_bf16.h>

// Per-block partial sums + completion counter (no allocation allowed).
#define MAX_BLOCKS 2048
__device__ double g_partial_c[MAX_BLOCKS];
__device__ double g_partial_r[MAX_BLOCKS];
__device__ unsigned int g_done = 0;   // zero at module load; last block resets it

__device__ __forceinline__ float smooth_l1(float d) {
    float ad = fabsf(d);
    return (ad < 1.0f) ? 0.5f * d * d : ad - 0.5f;
}

// Branchless per-row work. CE(lbl=0) = softplus(cy-cx), CE(lbl=1) = softplus(cx-cy),
// softplus(u) = max(u,0) + log1p(exp(-|u|)); |u| = |cx-cy| independent of label.
__device__ __forceinline__ void row_work(int lbl, float cx, float cy,
                                         const float4& r, const float4& t,
                                         float& c_acc, float& r_acc) {
    float d  = cx - cy;
    float u  = (lbl == 1) ? d : -d;
    float sp = fmaxf(u, 0.0f) + log1pf(__expf(-fabsf(d)));
    c_acc += (lbl <= 1) ? sp : 0.0f;

    float s = smooth_l1(r.x - t.x) + smooth_l1(r.y - t.y)
            + smooth_l1(r.z - t.z) + smooth_l1(r.w - t.w);
    r_acc += (lbl == 1) ? (s * 0.25f) : 0.0f;
}

__global__ void __launch_bounds__(256, 6)
mbl_fused_kernel(const float4* __restrict__ cout2,   // 2 rows per float4
                 const float4* __restrict__ rout,
                 const int2*   __restrict__ cls2,    // 2 int32 labels
                 const float4* __restrict__ reg_t,
                 int n,
                 float* __restrict__ out) {
    float c_acc = 0.0f;
    float r_acc = 0.0f;

    int n2 = n >> 1;
    int idx = blockIdx.x * blockDim.x + threadIdx.x;
    int stride = gridDim.x * blockDim.x;

    for (int g = idx; g < n2; g += stride) {
        // ---- all loads unconditional & front-batched (6 consecutive LDGs) ----
        int2   lbl = cls2[g];
        float4 c   = cout2[g];
        int i0 = 2 * g;
        float4 r0 = rout[i0];
        float4 r1 = rout[i0 + 1];
        float4 t0 = reg_t[i0];
        float4 t1 = reg_t[i0 + 1];

        row_work(lbl.x, c.x, c.y, r0, t0, c_acc, r_acc);
        row_work(lbl.y, c.z, c.w, r1, t1, c_acc, r_acc);
    }

    // scalar tail (n odd)
    if ((n & 1) && idx == 0) {
        const int*    cls  = (const int*)cls2;
        const float2* cout = (const float2*)cout2;
        int i = n - 1;
        float2 c = cout[i];
        float4 r = rout[i];
        float4 t = reg_t[i];
        row_work(cls[i], c.x, c.y, r, t, c_acc, r_acc);
    }

    // ---- block reduction: float shuffles, double at warp-leader granularity ----
    #pragma unroll
    for (int off = 16; off > 0; off >>= 1) {
        c_acc += __shfl_down_sync(0xFFFFFFFFu, c_acc, off);
        r_acc += __shfl_down_sync(0xFFFFFFFFu, r_acc, off);
    }

    __shared__ double s_c[8];
    __shared__ double s_r[8];
    __shared__ int s_last;
    int lane = threadIdx.x & 31;
    int wid  = threadIdx.x >> 5;
    if (lane == 0) { s_c[wid] = (double)c_acc; s_r[wid] = (double)r_acc; }
    __syncthreads();

    if (threadIdx.x == 0) {
        double cc = 0.0, rr = 0.0;
        #pragma unroll
        for (int w = 0; w < 8; w++) { cc += s_c[w]; rr += s_r[w]; }
        g_partial_c[blockIdx.x] = cc;
        g_partial_r[blockIdx.x] = rr;
        __threadfence();
        unsigned int t = atomicAdd(&g_done, 1u);
        s_last = (t == gridDim.x - 1) ? 1 : 0;
    }
    __syncthreads();

    // ---- last block: reduce per-block partials and finalize ----
    if (s_last) {
        __threadfence();
        double cc = 0.0, rr = 0.0;
        for (int i = threadIdx.x; i < gridDim.x; i += blockDim.x) {
            cc += g_partial_c[i];
            rr += g_partial_r[i];
        }
        #pragma unroll
        for (int off = 16; off > 0; off >>= 1) {
            cc += __shfl_down_sync(0xFFFFFFFFu, cc, off);
            rr += __shfl_down_sync(0xFFFFFFFFu, rr, off);
        }
        if (lane == 0) { s_c[wid] = cc; s_r[wid] = rr; }
        __syncthreads();
        if (threadIdx.x == 0) {
            double fc = 0.0, fr = 0.0;
            #pragma unroll
            for (int w = 0; w < 8; w++) { fc += s_c[w]; fr += s_r[w]; }
            double closs = fc / 64.0;
            double rloss = fr / 16.0;
            out[0] = (float)closs;
            out[1] = (float)rloss;
            out[2] = (float)(closs + 10.0 * rloss);
            g_done = 0;   // reset for next graph replay
        }
    }
}

extern "C" void kernel_launch(void* const* d_in, const int* in_sizes, int n_in,
                              void* d_out, int out_size) {
    const float4* cout  = (const float4*)d_in[0];   // [N,2] f32
    const float4* rout  = (const float4*)d_in[1];   // [N,4] f32
    const int2*   cls_t = (const int2*)d_in[2];     // [N] int32
    const float4* reg_t = (const float4*)d_in[3];   // [N,4] f32
    float* out = (float*)d_out;

    int n = in_sizes[2];

    const int threads = 256;
    int n2 = n >> 1;
    int blocks = (n2 + threads - 1) / threads;
    if (blocks > 888) blocks = 888;   // 148 SMs * 6 CTAs -> single wave at occ 6
    if (blocks < 1) blocks = 1;
    mbl_fused_kernel<<<blocks, threads>>>(cout, rout, cls_t, reg_t, n, out);
}